// round 14
// baseline (speedup 1.0000x reference)
#include <cuda_runtime.h>
#include <cuda_fp16.h>
#include <cub/cub.cuh>

#define BB 4
#define CIN 1024
#define CMID 512
#define HH 64
#define WW 96
#define AA 9
#define NANCH (AA*HH*WW)
#define TOTAL (BB*NANCH)
#define PRE 6000
#define POST 300
#define MWORDS 94

#define PROW 104
#define PPAD 6912
#define PVALID 6864
#define KTOT 9216
#define NPASS 3
#define NSTG (NPASS*144)       /* 3 passes x 144 k-chunks of 64 */
#define DRAIN 18
#define SA_BYTES 16384         /* A: 128 rows x 128B */
#define SB_BYTES 16384         /* B: 64 k-rows x 256B (128 pos) */
#define STG (SA_BYTES + SB_BYTES)

__device__ __align__(256) __half g_fh[(size_t)2*3*BB*CIN*PPAD];   // [limb][dx][b][ci][PPAD]
__device__ __align__(256) __half g_wh[(size_t)2*CMID*KTOT];       // [limb][co][k]
__device__ __align__(256) float g_conv1p[(size_t)BB*CMID*PPAD];
__device__ float4 g_props[TOTAL];
__device__ unsigned long long g_keys[TOTAL];
__device__ unsigned long long g_keys_out[TOTAL];
__device__ int g_vals[TOTAL];
__device__ int g_vals_out[TOTAL];
__device__ float4 g_top[BB*PRE];
__device__ unsigned long long g_mask[(size_t)BB*PRE*MWORDS];
__device__ unsigned char g_temp[32u<<20];

__constant__ float c_WS[9] = {184.f,368.f,736.f,128.f,256.f,512.f, 88.f,176.f,352.f};
__constant__ float c_HS[9] = { 96.f,192.f,384.f,128.f,256.f,512.f,176.f,352.f,704.f};
__device__ const int PASS_SA[NPASS] = {0,0,1};
__device__ const int PASS_SB[NPASS] = {0,1,0};

__device__ __forceinline__ uint32_t smem_u32(const void* p) {
    uint32_t a;
    asm("{ .reg .u64 t; cvta.to.shared.u64 t, %1; cvt.u32.u64 %0, t; }" : "=r"(a) : "l"(p));
    return a;
}
#define CP16(d, g) asm volatile("cp.async.cg.shared.global [%0], [%1], 16;" :: "r"(d), "l"(g))
#define CPC()  asm volatile("cp.async.commit_group;" ::: "memory")
#define CPW1() asm volatile("cp.async.wait_group 1;" ::: "memory")
#define CPW0() asm volatile("cp.async.wait_group 0;" ::: "memory")
#define LDSM4(r, a) asm volatile("ldmatrix.sync.aligned.m8n8.x4.shared.b16 {%0,%1,%2,%3}, [%4];" \
    : "=r"((r)[0]), "=r"((r)[1]), "=r"((r)[2]), "=r"((r)[3]) : "r"(a))
#define LDSM4T(r, a) asm volatile("ldmatrix.sync.aligned.m8n8.x4.trans.shared.b16 {%0,%1,%2,%3}, [%4];" \
    : "=r"((r)[0]), "=r"((r)[1]), "=r"((r)[2]), "=r"((r)[3]) : "r"(a))
#define MMA(c, a, b0, b1) asm volatile( \
    "mma.sync.aligned.m16n8k16.row.col.f32.f16.f16.f32 {%0,%1,%2,%3},{%4,%5,%6,%7},{%8,%9},{%0,%1,%2,%3};" \
    : "+f"((c)[0]), "+f"((c)[1]), "+f"((c)[2]), "+f"((c)[3]) \
    : "r"((a)[0]), "r"((a)[1]), "r"((a)[2]), "r"((a)[3]), "r"(b0), "r"(b1))

// ---- P0: 2-limb weight split (x 2^12) ----
__global__ void split_w(const float* __restrict__ conv_w) {
    int idx = blockIdx.x * blockDim.x + threadIdx.x;
    if (idx >= CMID*CIN*9) return;
    int tap = idx % 9;
    int r = idx / 9;
    int ci = r % CIN, co = r / CIN;
    float xs = conv_w[idx] * 4096.f;
    __half h1 = __float2half_rn(xs);
    __half h2 = __float2half_rn(xs - __half2float(h1));
    size_t o = (size_t)co*KTOT + tap*CIN + ci;
    g_wh[o] = h1;
    g_wh[(size_t)CMID*KTOT + o] = h2;
}

// ---- P1: 2-limb feature split (x 2^12), 3 dx-shifted padded copies ----
__global__ void split_feat(const float* __restrict__ feat) {
    size_t idx = (size_t)blockIdx.x * blockDim.x + threadIdx.x;
    if (idx >= (size_t)3*BB*CIN*PPAD) return;
    int q = (int)(idx % PPAD);
    size_t r = idx / PPAD;
    int ci = (int)(r % CIN); r /= CIN;
    int b = (int)(r % BB);
    int dx = (int)(r / BB);
    int j = q + dx;
    float x = 0.f;
    int hp = j / PROW, wp = j % PROW;
    if (j < PVALID && hp >= 1 && hp <= HH && wp >= 1 && wp <= WW)
        x = feat[(((size_t)b*CIN + ci)*HH + hp - 1)*WW + wp - 1];
    x *= 4096.f;
    __half h1 = __float2half_rn(x);
    __half h2 = __float2half_rn(x - __half2float(h1));
    size_t ss = (size_t)3*BB*CIN*PPAD;
    size_t o = (((size_t)dx*BB + b)*CIN + ci)*PPAD + q;
    g_fh[o] = h1;
    g_fh[ss + o] = h2;
}

// ---- K1: implicit-GEMM conv, HMMA 128x128 tile, chunked accumulation ----
__device__ __forceinline__ void stage_src(int s, int b, int co0, int pos0,
                                          const __half*& gA, const __half*& gB) {
    int p = s / 144, ks = s - p*144;
    int k0 = ks * 64;
    int tap = k0 >> 10, ci0 = k0 & 1023;
    int dy = tap / 3, dx = tap - dy*3;
    int sa = PASS_SA[p], sb = PASS_SB[p];
    gA = g_wh + (size_t)sa*CMID*KTOT + (size_t)co0*KTOT + k0;
    gB = g_fh + (size_t)sb*((size_t)3*BB*CIN*PPAD) +
         (((size_t)dx*BB + b)*CIN + ci0)*PPAD + pos0 + dy*PROW;
}

__device__ __forceinline__ void load_stage(uint32_t sbuf,
                                           const __half* gA, const __half* gB, int t) {
    #pragma unroll
    for (int i = 0; i < 4; ++i) {            // A: 128 rows x 128B, 16B chunks
        int id = t + i*256, row = id >> 3, c = id & 7;
        CP16(sbuf + row*128 + ((c*16) ^ ((row & 7) << 4)), gA + (size_t)row*KTOT + c*8);
    }
    #pragma unroll
    for (int i = 0; i < 4; ++i) {            // B: 64 k-rows x 256B, 16B chunks
        int id = t + i*256, k = id >> 4, c = id & 15;
        CP16(sbuf + SA_BYTES + k*256 + ((c*16) ^ ((k & 7) << 4)), gB + (size_t)k*PPAD + c*8);
    }
}

__global__ __launch_bounds__(256) void gemm_conv(const float* __restrict__ bias) {
    extern __shared__ __align__(256) char smem[];
    const uint32_t sbase = smem_u32(smem);
    const int t = threadIdx.x, lane = t & 31, wid = t >> 5;
    const int wm = wid & 1, wn = wid >> 1;   // warp tile: 64co x 32pos
    const int cot = blockIdx.x & 3;
    const int rest = blockIdx.x >> 2;
    const int post = rest % 52;
    const int b = rest / 52;
    const int co0 = cot*128, pos0 = post*128;

    float acc[4][4][4];
    float accS[4][4][4];
    #pragma unroll
    for (int i = 0; i < 4; ++i)
        #pragma unroll
        for (int j = 0; j < 4; ++j)
            #pragma unroll
            for (int k = 0; k < 4; ++k) { acc[i][j][k] = 0.f; accS[i][j][k] = 0.f; }

    const __half *gA, *gB;
    stage_src(0, b, co0, pos0, gA, gB);
    load_stage(sbase, gA, gB, t);
    CPC();

    for (int s = 0; s < NSTG; ++s) {
        const int buf = s & 1;
        if (s + 1 < NSTG) {
            stage_src(s + 1, b, co0, pos0, gA, gB);
            load_stage(sbase + ((s + 1) & 1)*STG, gA, gB, t);
            CPC();
            CPW1();
        } else {
            CPW0();
        }
        __syncthreads();
        const uint32_t sA = sbase + buf*STG, sB = sA + SA_BYTES;
        #pragma unroll
        for (int kk = 0; kk < 4; ++kk) {
            uint32_t a[4][4], bb[2][4];
            #pragma unroll
            for (int i = 0; i < 4; ++i) {
                int row = wm*64 + i*16 + (lane & 15);
                uint32_t ad = sA + row*128 +
                    (((kk*32) + ((lane >> 4) << 4)) ^ ((row & 7) << 4));
                LDSM4(a[i], ad);
            }
            #pragma unroll
            for (int jp = 0; jp < 2; ++jp) {
                int kr = kk*16 + (lane & 15);
                uint32_t nb = (wn*32 + jp*16)*2 + ((lane >> 4) << 4);
                uint32_t ad = sB + kr*256 + (nb ^ ((kr & 7) << 4));
                LDSM4T(bb[jp], ad);
            }
            #pragma unroll
            for (int i = 0; i < 4; ++i)
                #pragma unroll
                for (int j = 0; j < 4; ++j)
                    MMA(acc[i][j], a[i], bb[j >> 1][(j & 1)*2], bb[j >> 1][(j & 1)*2 + 1]);
        }
        if ((s % DRAIN) == DRAIN - 1) {
            #pragma unroll
            for (int i = 0; i < 4; ++i)
                #pragma unroll
                for (int j = 0; j < 4; ++j)
                    #pragma unroll
                    for (int k = 0; k < 4; ++k) {
                        accS[i][j][k] += acc[i][j][k];
                        acc[i][j][k] = 0.f;
                    }
        }
        __syncthreads();
    }

    const float SC = 1.f / 16777216.f;       // 2^-24 (both operands x 2^12)
    #pragma unroll
    for (int i = 0; i < 4; ++i) {
        int co = co0 + wm*64 + i*16 + (lane >> 2);
        float bv0 = bias[co], bv8 = bias[co + 8];
        float* r0 = g_conv1p + ((size_t)b*CMID + co)*PPAD;
        #pragma unroll
        for (int j = 0; j < 4; ++j) {
            int pos = pos0 + wn*32 + j*8 + (lane & 3)*2;
            float2 v0, v1;
            v0.x = fmaxf(fmaf(accS[i][j][0] + acc[i][j][0], SC, bv0), 0.f);
            v0.y = fmaxf(fmaf(accS[i][j][1] + acc[i][j][1], SC, bv0), 0.f);
            v1.x = fmaxf(fmaf(accS[i][j][2] + acc[i][j][2], SC, bv8), 0.f);
            v1.y = fmaxf(fmaf(accS[i][j][3] + acc[i][j][3], SC, bv8), 0.f);
            *(float2*)(r0 + pos) = v0;
            *(float2*)(r0 + 8*PPAD + pos) = v1;
        }
    }
}

// ---- K2: 1x1 heads + softmax + decode + clip + sort keys ----
__global__ __launch_bounds__(288) void heads_kernel(const float* __restrict__ cls_w,
        const float* __restrict__ cls_b, const float* __restrict__ bbox_w,
        const float* __restrict__ bbox_b, const float* __restrict__ im_info) {
    extern __shared__ float sm[];
    float* wsm = sm;
    float* fsm = sm + 54*512;
    const int b = blockIdx.x / HH, h = blockIdx.x % HH;
    const int t = threadIdx.x, a = t / 32, lane = t % 32;

    for (int i = t; i < 18*512; i += 288) wsm[i] = cls_w[i];
    for (int i = t; i < 36*512; i += 288) wsm[18*512 + i] = bbox_w[i];

    float acc[6][3];
    #pragma unroll
    for (int o = 0; o < 6; ++o)
        #pragma unroll
        for (int q = 0; q < 3; ++q) acc[o][q] = 0.f;

    const float* w0 = wsm + a*512;
    const float* w1 = wsm + (a+9)*512;
    const float* wd = wsm + (18 + a*4)*512;

    for (int ct = 0; ct < 8; ++ct) {
        __syncthreads();
        for (int i = t; i < 64*96; i += 288)
            fsm[i] = g_conv1p[((size_t)b*CMID + ct*64 + i/96)*PPAD + h*PROW + (i%96)];
        __syncthreads();
        #pragma unroll 4
        for (int cl = 0; cl < 64; ++cl) {
            int ch = ct*64 + cl;
            float v0 = w0[ch], v1 = w1[ch];
            float v2 = wd[ch], v3 = wd[512+ch], v4 = wd[1024+ch], v5 = wd[1536+ch];
            #pragma unroll
            for (int q = 0; q < 3; ++q) {
                float f = fsm[cl*96 + lane + q*32];
                acc[0][q] = fmaf(v0, f, acc[0][q]);
                acc[1][q] = fmaf(v1, f, acc[1][q]);
                acc[2][q] = fmaf(v2, f, acc[2][q]);
                acc[3][q] = fmaf(v3, f, acc[3][q]);
                acc[4][q] = fmaf(v4, f, acc[4][q]);
                acc[5][q] = fmaf(v5, f, acc[5][q]);
            }
        }
    }
    const float imh = im_info[b*3+0] - 1.f, imw = im_info[b*3+1] - 1.f;
    const float cb0 = cls_b[a], cb1 = cls_b[a+9];
    const float bb0 = bbox_b[a*4+0], bb1 = bbox_b[a*4+1];
    const float bb2 = bbox_b[a*4+2], bb3 = bbox_b[a*4+3];
    const float ws_ = c_WS[a], hs_ = c_HS[a];
    #pragma unroll
    for (int q = 0; q < 3; ++q) {
        int w = lane + q*32;
        float s0 = acc[0][q] + cb0, s1 = acc[1][q] + cb1;
        float m = fmaxf(s0, s1);
        float e0 = expf(s0 - m), e1 = expf(s1 - m);
        float score = e1 / (e0 + e1);
        float d0 = acc[2][q] + bb0, d1 = acc[3][q] + bb1;
        float d2 = acc[4][q] + bb2, d3 = acc[5][q] + bb3;
        float ax1 = 16.f*w + (7.5f - 0.5f*(ws_-1.f));
        float ay1 = 16.f*h + (7.5f - 0.5f*(hs_-1.f));
        float cx = d0*ws_ + ax1 + 0.5f*ws_;
        float cy = d1*hs_ + ay1 + 0.5f*hs_;
        float pw = expf(d2)*ws_, ph = expf(d3)*hs_;
        float x1 = fminf(fmaxf(cx - 0.5f*pw, 0.f), imw);
        float y1 = fminf(fmaxf(cy - 0.5f*ph, 0.f), imh);
        float x2 = fminf(fmaxf(cx + 0.5f*pw, 0.f), imw);
        float y2 = fminf(fmaxf(cy + 0.5f*ph, 0.f), imh);
        int pidx = (h*WW + w)*AA + a;
        int gi = b*NANCH + pidx;
        g_props[gi] = make_float4(x1, y1, x2, y2);
        unsigned u = __float_as_uint(score);
        u = (u & 0x80000000u) ? ~u : (u | 0x80000000u);
        g_keys[gi] = ((unsigned long long)b << 32) | (unsigned)(~u);
        g_vals[gi] = pidx;
    }
}

__global__ void gather_kernel() {
    int t = blockIdx.x * blockDim.x + threadIdx.x;
    if (t >= BB*PRE) return;
    int b = t / PRE, r = t % PRE;
    g_top[t] = g_props[b*NANCH + g_vals_out[b*NANCH + r]];
}

// ---- K4: NMS mask, upper triangle only (j >= own word start) ----
__global__ __launch_bounds__(256) void mask_kernel() {
    int t = blockIdx.x * blockDim.x + threadIdx.x;
    if (t >= BB*PRE) return;
    int b = t / PRE, r = t % PRE;
    float4 bi = g_top[t];
    float ai = (bi.z - bi.x + 1.f) * (bi.w - bi.y + 1.f);
    const float4* base = g_top + b*PRE;
    unsigned long long* mrow = g_mask + (size_t)t*MWORDS;
    const int w0 = r >> 6;
    for (int w = 0; w < w0; ++w) mrow[w] = 0;      // bits j<i never consulted
    unsigned long long word = 0;
    for (int j = w0 << 6; j < PRE; ++j) {
        float4 bj = __ldg(&base[j]);
        float xx1 = fmaxf(bi.x, bj.x), yy1 = fmaxf(bi.y, bj.y);
        float xx2 = fminf(bi.z, bj.z), yy2 = fminf(bi.w, bj.w);
        float inter = fmaxf(xx2 - xx1 + 1.f, 0.f) * fmaxf(yy2 - yy1 + 1.f, 0.f);
        float aj = (bj.z - bj.x + 1.f) * (bj.w - bj.y + 1.f);
        float iou = __fdiv_rn(inter, ai + aj - inter);
        if (!(iou <= 0.7f)) word |= (1ULL << (j & 63));
        if ((j & 63) == 63) {
            if ((j >> 6) == w0) word &= ~((1ULL << (r & 63)) - 1ULL);  // clear j<r
            mrow[j >> 6] = word;
            word = 0;
        }
    }
    mrow[MWORDS - 1] = word;                        // tail (bits 0..47)
}

__device__ __forceinline__ unsigned long long shfl64(unsigned long long v, int src) {
    return __shfl_sync(0xffffffffu, v, src);
}

__global__ void nms_scan(float* __restrict__ out) {
    const int b = blockIdx.x, lane = threadIdx.x;
    __shared__ int keeps[POST];
    const unsigned long long* mbase = g_mask + (size_t)b*PRE*MWORDS;
    unsigned long long r0 = 0, r1 = 0, r2 = 0;
    int cnt = 0;
    for (int w = 0; w < MWORDS && cnt < POST; ++w) {
        int src = w & 31;
        unsigned long long cur = (w < 32) ? r0 : (w < 64 ? r1 : r2);
        unsigned long long avail = ~shfl64(cur, src);
        if (w == MWORDS - 1) avail &= (1ULL << 48) - 1;
        while (avail && cnt < POST) {
            int bit = __ffsll((long long)avail) - 1;
            int i = (w << 6) + bit;
            keeps[cnt++] = i;
            const unsigned long long* row = mbase + (size_t)i*MWORDS;
            r0 |= row[lane];
            r1 |= row[lane + 32];
            if (lane < 30) r2 |= row[lane + 64];
            unsigned long long cur2 = (w < 32) ? r0 : (w < 64 ? r1 : r2);
            avail &= ~shfl64(cur2, src);
        }
    }
    __syncwarp();
    for (int k = lane; k < POST; k += 32) {
        float4 bx = make_float4(0.f, 0.f, 0.f, 0.f);
        if (k < cnt) bx = g_top[b*PRE + keeps[k]];
        float* o = out + ((size_t)b*POST + k)*5;
        o[0] = (float)b; o[1] = bx.x; o[2] = bx.y; o[3] = bx.z; o[4] = bx.w;
    }
}

extern "C" void kernel_launch(void* const* d_in, const int* in_sizes, int n_in,
                              void* d_out, int out_size) {
    const float* base_feat = (const float*)d_in[0];
    const float* im_info   = (const float*)d_in[1];
    const float* conv_w    = (const float*)d_in[4];
    const float* conv_b    = (const float*)d_in[5];
    const float* cls_w     = (const float*)d_in[6];
    const float* cls_b     = (const float*)d_in[7];
    const float* bbox_w    = (const float*)d_in[8];
    const float* bbox_b    = (const float*)d_in[9];
    float* out = (float*)d_out;

    split_w<<<(CMID*CIN*9 + 255)/256, 256>>>(conv_w);
    size_t fsn = (size_t)3*BB*CIN*PPAD;
    split_feat<<<(unsigned)((fsn + 255)/256), 256>>>(base_feat);

    cudaFuncSetAttribute(gemm_conv, cudaFuncAttributeMaxDynamicSharedMemorySize, 2*STG);
    gemm_conv<<<4*52*BB, 256, 2*STG>>>(conv_b);

    size_t hsmem = (size_t)(54*512 + 64*96) * sizeof(float);
    cudaFuncSetAttribute(heads_kernel, cudaFuncAttributeMaxDynamicSharedMemorySize, (int)hsmem);
    heads_kernel<<<BB*HH, 288, hsmem>>>(cls_w, cls_b, bbox_w, bbox_b, im_info);

    void *d_temp, *dk, *dko, *dv, *dvo;
    cudaGetSymbolAddress(&d_temp, g_temp);
    cudaGetSymbolAddress(&dk, g_keys);
    cudaGetSymbolAddress(&dko, g_keys_out);
    cudaGetSymbolAddress(&dv, g_vals);
    cudaGetSymbolAddress(&dvo, g_vals_out);
    size_t temp_bytes = sizeof(g_temp);
    cub::DeviceRadixSort::SortPairs(d_temp, temp_bytes,
        (const unsigned long long*)dk, (unsigned long long*)dko,
        (const int*)dv, (int*)dvo, TOTAL, 0, 34, (cudaStream_t)0);

    gather_kernel<<<(BB*PRE + 255)/256, 256>>>();
    mask_kernel<<<(BB*PRE + 255)/256, 256>>>();
    nms_scan<<<BB, 32>>>(out);
    (void)in_sizes; (void)n_in; (void)out_size;
}

// round 15
// speedup vs baseline: 1.0435x; 1.0435x over previous
#include <cuda_runtime.h>
#include <cuda_fp16.h>
#include <cub/cub.cuh>

#define BB 4
#define CIN 1024
#define CMID 512
#define HH 64
#define WW 96
#define AA 9
#define NANCH (AA*HH*WW)
#define TOTAL (BB*NANCH)
#define PRE 6000
#define POST 300
#define MWORDS 94

#define PROW 104
#define PPAD 6912
#define PVALID 6864
#define KTOT 9216
#define NPASS 3
#define NSTG (NPASS*144)       /* 3 passes x 144 k-chunks of 64 */
#define DRAIN 18
#define SA_BYTES 16384         /* A: 128 rows x 128B */
#define SB_BYTES 8192          /* B: 64 k-rows x 128B (64 pos) */
#define STG (SA_BYTES + SB_BYTES)

__device__ __align__(256) __half g_fh[(size_t)2*3*BB*CIN*PPAD];   // [limb][dx][b][ci][PPAD]
__device__ __align__(256) __half g_wh[(size_t)2*CMID*KTOT];       // [limb][co][k]
__device__ __align__(256) float g_conv1p[(size_t)BB*CMID*PPAD];
__device__ float4 g_props[TOTAL];
__device__ unsigned long long g_keys[TOTAL];
__device__ unsigned long long g_keys_out[TOTAL];
__device__ int g_vals[TOTAL];
__device__ int g_vals_out[TOTAL];
__device__ float4 g_top[BB*PRE];
__device__ unsigned long long g_mask[(size_t)BB*PRE*MWORDS];
__device__ unsigned char g_temp[32u<<20];

__constant__ float c_WS[9] = {184.f,368.f,736.f,128.f,256.f,512.f, 88.f,176.f,352.f};
__constant__ float c_HS[9] = { 96.f,192.f,384.f,128.f,256.f,512.f,176.f,352.f,704.f};
__device__ const int PASS_SA[NPASS] = {0,0,1};
__device__ const int PASS_SB[NPASS] = {0,1,0};

__device__ __forceinline__ uint32_t smem_u32(const void* p) {
    uint32_t a;
    asm("{ .reg .u64 t; cvta.to.shared.u64 t, %1; cvt.u32.u64 %0, t; }" : "=r"(a) : "l"(p));
    return a;
}
#define CP16(d, g) asm volatile("cp.async.cg.shared.global [%0], [%1], 16;" :: "r"(d), "l"(g))
#define CPC()  asm volatile("cp.async.commit_group;" ::: "memory")
#define CPW1() asm volatile("cp.async.wait_group 1;" ::: "memory")
#define CPW0() asm volatile("cp.async.wait_group 0;" ::: "memory")
#define LDSM4(r, a) asm volatile("ldmatrix.sync.aligned.m8n8.x4.shared.b16 {%0,%1,%2,%3}, [%4];" \
    : "=r"((r)[0]), "=r"((r)[1]), "=r"((r)[2]), "=r"((r)[3]) : "r"(a))
#define LDSM4T(r, a) asm volatile("ldmatrix.sync.aligned.m8n8.x4.trans.shared.b16 {%0,%1,%2,%3}, [%4];" \
    : "=r"((r)[0]), "=r"((r)[1]), "=r"((r)[2]), "=r"((r)[3]) : "r"(a))
#define MMA(c, a, b0, b1) asm volatile( \
    "mma.sync.aligned.m16n8k16.row.col.f32.f16.f16.f32 {%0,%1,%2,%3},{%4,%5,%6,%7},{%8,%9},{%0,%1,%2,%3};" \
    : "+f"((c)[0]), "+f"((c)[1]), "+f"((c)[2]), "+f"((c)[3]) \
    : "r"((a)[0]), "r"((a)[1]), "r"((a)[2]), "r"((a)[3]), "r"(b0), "r"(b1))

// ---- P0: 2-limb weight split (x 2^12) ----
__global__ void split_w(const float* __restrict__ conv_w) {
    int idx = blockIdx.x * blockDim.x + threadIdx.x;
    if (idx >= CMID*CIN*9) return;
    int tap = idx % 9;
    int r = idx / 9;
    int ci = r % CIN, co = r / CIN;
    float xs = conv_w[idx] * 4096.f;
    __half h1 = __float2half_rn(xs);
    __half h2 = __float2half_rn(xs - __half2float(h1));
    size_t o = (size_t)co*KTOT + tap*CIN + ci;
    g_wh[o] = h1;
    g_wh[(size_t)CMID*KTOT + o] = h2;
}

// ---- P1: 2-limb feature split (x 2^12), 3 dx-shifted padded copies ----
__global__ void split_feat(const float* __restrict__ feat) {
    size_t idx = (size_t)blockIdx.x * blockDim.x + threadIdx.x;
    if (idx >= (size_t)3*BB*CIN*PPAD) return;
    int q = (int)(idx % PPAD);
    size_t r = idx / PPAD;
    int ci = (int)(r % CIN); r /= CIN;
    int b = (int)(r % BB);
    int dx = (int)(r / BB);
    int j = q + dx;
    float x = 0.f;
    int hp = j / PROW, wp = j % PROW;
    if (j < PVALID && hp >= 1 && hp <= HH && wp >= 1 && wp <= WW)
        x = feat[(((size_t)b*CIN + ci)*HH + hp - 1)*WW + wp - 1];
    x *= 4096.f;
    __half h1 = __float2half_rn(x);
    __half h2 = __float2half_rn(x - __half2float(h1));
    size_t ss = (size_t)3*BB*CIN*PPAD;
    size_t o = (((size_t)dx*BB + b)*CIN + ci)*PPAD + q;
    g_fh[o] = h1;
    g_fh[ss + o] = h2;
}

// ---- K1: implicit-GEMM conv, HMMA BK=64 128x64 tile (round-13 verbatim) ----
__device__ __forceinline__ void stage_src(int s, int b, int co0, int pos0,
                                          const __half*& gA, const __half*& gB) {
    int p = s / 144, ks = s - p*144;
    int k0 = ks * 64;
    int tap = k0 >> 10, ci0 = k0 & 1023;
    int dy = tap / 3, dx = tap - dy*3;
    int sa = PASS_SA[p], sb = PASS_SB[p];
    gA = g_wh + (size_t)sa*CMID*KTOT + (size_t)co0*KTOT + k0;
    gB = g_fh + (size_t)sb*((size_t)3*BB*CIN*PPAD) +
         (((size_t)dx*BB + b)*CIN + ci0)*PPAD + pos0 + dy*PROW;
}

__device__ __forceinline__ void load_stage(uint32_t sbuf,
                                           const __half* gA, const __half* gB, int t) {
    #pragma unroll
    for (int i = 0; i < 4; ++i) {            // A: 128 rows x 128B, 16B chunks
        int id = t + i*256, row = id >> 3, c = id & 7;
        CP16(sbuf + row*128 + ((c*16) ^ ((row & 7) << 4)), gA + (size_t)row*KTOT + c*8);
    }
    #pragma unroll
    for (int i = 0; i < 2; ++i) {            // B: 64 k-rows x 128B, 16B chunks
        int id = t + i*256, k = id >> 3, c = id & 7;
        CP16(sbuf + SA_BYTES + k*128 + ((c*16) ^ ((k & 7) << 4)), gB + (size_t)k*PPAD + c*8);
    }
}

__global__ __launch_bounds__(256) void gemm_conv(const float* __restrict__ bias) {
    __shared__ __align__(256) char smem[2*STG];   // 48KB static
    const uint32_t sbase = smem_u32(smem);
    const int t = threadIdx.x, lane = t & 31, wid = t >> 5;
    const int wm = wid & 1, wn = wid >> 1;   // warp tile: 64co x 16pos
    const int cot = blockIdx.x & 3;
    const int rest = blockIdx.x >> 2;
    const int post = rest % 104;
    const int b = rest / 104;
    const int co0 = cot*128, pos0 = post*64;

    float acc[4][2][4];
    float accS[4][2][4];
    #pragma unroll
    for (int i = 0; i < 4; ++i)
        #pragma unroll
        for (int j = 0; j < 2; ++j)
            #pragma unroll
            for (int k = 0; k < 4; ++k) { acc[i][j][k] = 0.f; accS[i][j][k] = 0.f; }

    const __half *gA, *gB;
    stage_src(0, b, co0, pos0, gA, gB);
    load_stage(sbase, gA, gB, t);
    CPC();

    for (int s = 0; s < NSTG; ++s) {
        const int buf = s & 1;
        if (s + 1 < NSTG) {
            stage_src(s + 1, b, co0, pos0, gA, gB);
            load_stage(sbase + ((s + 1) & 1)*STG, gA, gB, t);
            CPC();
            CPW1();
        } else {
            CPW0();
        }
        __syncthreads();
        const uint32_t sA = sbase + buf*STG, sB = sA + SA_BYTES;
        #pragma unroll
        for (int kk = 0; kk < 4; ++kk) {
            uint32_t a[4][4], bb[4];
            #pragma unroll
            for (int i = 0; i < 4; ++i) {
                int row = wm*64 + i*16 + (lane & 15);
                uint32_t ad = sA + row*128 +
                    (((kk*32) + ((lane >> 4) << 4)) ^ ((row & 7) << 4));
                LDSM4(a[i], ad);
            }
            {
                int kr = kk*16 + (lane & 15);
                uint32_t nb = wn*32 + ((lane >> 4) << 4);
                uint32_t ad = sB + kr*128 + (nb ^ ((kr & 7) << 4));
                LDSM4T(bb, ad);
            }
            #pragma unroll
            for (int i = 0; i < 4; ++i) {
                MMA(acc[i][0], a[i], bb[0], bb[1]);
                MMA(acc[i][1], a[i], bb[2], bb[3]);
            }
        }
        if ((s % DRAIN) == DRAIN - 1) {
            #pragma unroll
            for (int i = 0; i < 4; ++i)
                #pragma unroll
                for (int j = 0; j < 2; ++j)
                    #pragma unroll
                    for (int k = 0; k < 4; ++k) {
                        accS[i][j][k] += acc[i][j][k];
                        acc[i][j][k] = 0.f;
                    }
        }
        __syncthreads();
    }

    const float SC = 1.f / 16777216.f;       // 2^-24 (both operands x 2^12)
    #pragma unroll
    for (int i = 0; i < 4; ++i) {
        int co = co0 + wm*64 + i*16 + (lane >> 2);
        float bv0 = bias[co], bv8 = bias[co + 8];
        float* r0 = g_conv1p + ((size_t)b*CMID + co)*PPAD;
        #pragma unroll
        for (int j = 0; j < 2; ++j) {
            int pos = pos0 + wn*16 + j*8 + (lane & 3)*2;
            float2 v0, v1;
            v0.x = fmaxf(fmaf(accS[i][j][0] + acc[i][j][0], SC, bv0), 0.f);
            v0.y = fmaxf(fmaf(accS[i][j][1] + acc[i][j][1], SC, bv0), 0.f);
            v1.x = fmaxf(fmaf(accS[i][j][2] + acc[i][j][2], SC, bv8), 0.f);
            v1.y = fmaxf(fmaf(accS[i][j][3] + acc[i][j][3], SC, bv8), 0.f);
            *(float2*)(r0 + pos) = v0;
            *(float2*)(r0 + 8*PPAD + pos) = v1;
        }
    }
}

// ---- K2: 1x1 heads + softmax + decode + clip + sort keys ----
__global__ __launch_bounds__(288) void heads_kernel(const float* __restrict__ cls_w,
        const float* __restrict__ cls_b, const float* __restrict__ bbox_w,
        const float* __restrict__ bbox_b, const float* __restrict__ im_info) {
    extern __shared__ float sm[];
    float* wsm = sm;
    float* fsm = sm + 54*512;
    const int b = blockIdx.x / HH, h = blockIdx.x % HH;
    const int t = threadIdx.x, a = t / 32, lane = t % 32;

    for (int i = t; i < 18*512; i += 288) wsm[i] = cls_w[i];
    for (int i = t; i < 36*512; i += 288) wsm[18*512 + i] = bbox_w[i];

    float acc[6][3];
    #pragma unroll
    for (int o = 0; o < 6; ++o)
        #pragma unroll
        for (int q = 0; q < 3; ++q) acc[o][q] = 0.f;

    const float* w0 = wsm + a*512;
    const float* w1 = wsm + (a+9)*512;
    const float* wd = wsm + (18 + a*4)*512;

    for (int ct = 0; ct < 8; ++ct) {
        __syncthreads();
        for (int i = t; i < 64*96; i += 288)
            fsm[i] = g_conv1p[((size_t)b*CMID + ct*64 + i/96)*PPAD + h*PROW + (i%96)];
        __syncthreads();
        #pragma unroll 4
        for (int cl = 0; cl < 64; ++cl) {
            int ch = ct*64 + cl;
            float v0 = w0[ch], v1 = w1[ch];
            float v2 = wd[ch], v3 = wd[512+ch], v4 = wd[1024+ch], v5 = wd[1536+ch];
            #pragma unroll
            for (int q = 0; q < 3; ++q) {
                float f = fsm[cl*96 + lane + q*32];
                acc[0][q] = fmaf(v0, f, acc[0][q]);
                acc[1][q] = fmaf(v1, f, acc[1][q]);
                acc[2][q] = fmaf(v2, f, acc[2][q]);
                acc[3][q] = fmaf(v3, f, acc[3][q]);
                acc[4][q] = fmaf(v4, f, acc[4][q]);
                acc[5][q] = fmaf(v5, f, acc[5][q]);
            }
        }
    }
    const float imh = im_info[b*3+0] - 1.f, imw = im_info[b*3+1] - 1.f;
    const float cb0 = cls_b[a], cb1 = cls_b[a+9];
    const float bb0 = bbox_b[a*4+0], bb1 = bbox_b[a*4+1];
    const float bb2 = bbox_b[a*4+2], bb3 = bbox_b[a*4+3];
    const float ws_ = c_WS[a], hs_ = c_HS[a];
    #pragma unroll
    for (int q = 0; q < 3; ++q) {
        int w = lane + q*32;
        float s0 = acc[0][q] + cb0, s1 = acc[1][q] + cb1;
        float m = fmaxf(s0, s1);
        float e0 = expf(s0 - m), e1 = expf(s1 - m);
        float score = e1 / (e0 + e1);
        float d0 = acc[2][q] + bb0, d1 = acc[3][q] + bb1;
        float d2 = acc[4][q] + bb2, d3 = acc[5][q] + bb3;
        float ax1 = 16.f*w + (7.5f - 0.5f*(ws_-1.f));
        float ay1 = 16.f*h + (7.5f - 0.5f*(hs_-1.f));
        float cx = d0*ws_ + ax1 + 0.5f*ws_;
        float cy = d1*hs_ + ay1 + 0.5f*hs_;
        float pw = expf(d2)*ws_, ph = expf(d3)*hs_;
        float x1 = fminf(fmaxf(cx - 0.5f*pw, 0.f), imw);
        float y1 = fminf(fmaxf(cy - 0.5f*ph, 0.f), imh);
        float x2 = fminf(fmaxf(cx + 0.5f*pw, 0.f), imw);
        float y2 = fminf(fmaxf(cy + 0.5f*ph, 0.f), imh);
        int pidx = (h*WW + w)*AA + a;
        int gi = b*NANCH + pidx;
        g_props[gi] = make_float4(x1, y1, x2, y2);
        unsigned u = __float_as_uint(score);
        u = (u & 0x80000000u) ? ~u : (u | 0x80000000u);
        g_keys[gi] = ((unsigned long long)b << 32) | (unsigned)(~u);
        g_vals[gi] = pidx;
    }
}

__global__ void gather_kernel() {
    int t = blockIdx.x * blockDim.x + threadIdx.x;
    if (t >= BB*PRE) return;
    int b = t / PRE, r = t % PRE;
    g_top[t] = g_props[b*NANCH + g_vals_out[b*NANCH + r]];
}

// ---- K4: NMS mask, upper triangle only ----
__global__ __launch_bounds__(256) void mask_kernel() {
    int t = blockIdx.x * blockDim.x + threadIdx.x;
    if (t >= BB*PRE) return;
    int b = t / PRE, r = t % PRE;
    float4 bi = g_top[t];
    float ai = (bi.z - bi.x + 1.f) * (bi.w - bi.y + 1.f);
    const float4* base = g_top + b*PRE;
    unsigned long long* mrow = g_mask + (size_t)t*MWORDS;
    const int w0 = r >> 6;
    for (int w = 0; w < w0; ++w) mrow[w] = 0;      // bits j<i never consulted
    unsigned long long word = 0;
    for (int j = w0 << 6; j < PRE; ++j) {
        float4 bj = __ldg(&base[j]);
        float xx1 = fmaxf(bi.x, bj.x), yy1 = fmaxf(bi.y, bj.y);
        float xx2 = fminf(bi.z, bj.z), yy2 = fminf(bi.w, bj.w);
        float inter = fmaxf(xx2 - xx1 + 1.f, 0.f) * fmaxf(yy2 - yy1 + 1.f, 0.f);
        float aj = (bj.z - bj.x + 1.f) * (bj.w - bj.y + 1.f);
        float iou = __fdiv_rn(inter, ai + aj - inter);
        if (!(iou <= 0.7f)) word |= (1ULL << (j & 63));
        if ((j & 63) == 63) {
            if ((j >> 6) == w0) word &= ~((1ULL << (r & 63)) - 1ULL);  // clear j<r
            mrow[j >> 6] = word;
            word = 0;
        }
    }
    mrow[MWORDS - 1] = word;                        // tail (bits 0..47)
}

__device__ __forceinline__ unsigned long long shfl64(unsigned long long v, int src) {
    return __shfl_sync(0xffffffffu, v, src);
}

__global__ void nms_scan(float* __restrict__ out) {
    const int b = blockIdx.x, lane = threadIdx.x;
    __shared__ int keeps[POST];
    const unsigned long long* mbase = g_mask + (size_t)b*PRE*MWORDS;
    unsigned long long r0 = 0, r1 = 0, r2 = 0;
    int cnt = 0;
    for (int w = 0; w < MWORDS && cnt < POST; ++w) {
        int src = w & 31;
        unsigned long long cur = (w < 32) ? r0 : (w < 64 ? r1 : r2);
        unsigned long long avail = ~shfl64(cur, src);
        if (w == MWORDS - 1) avail &= (1ULL << 48) - 1;
        while (avail && cnt < POST) {
            int bit = __ffsll((long long)avail) - 1;
            int i = (w << 6) + bit;
            keeps[cnt++] = i;
            const unsigned long long* row = mbase + (size_t)i*MWORDS;
            r0 |= row[lane];
            r1 |= row[lane + 32];
            if (lane < 30) r2 |= row[lane + 64];
            unsigned long long cur2 = (w < 32) ? r0 : (w < 64 ? r1 : r2);
            avail &= ~shfl64(cur2, src);
        }
    }
    __syncwarp();
    for (int k = lane; k < POST; k += 32) {
        float4 bx = make_float4(0.f, 0.f, 0.f, 0.f);
        if (k < cnt) bx = g_top[b*PRE + keeps[k]];
        float* o = out + ((size_t)b*POST + k)*5;
        o[0] = (float)b; o[1] = bx.x; o[2] = bx.y; o[3] = bx.z; o[4] = bx.w;
    }
}

extern "C" void kernel_launch(void* const* d_in, const int* in_sizes, int n_in,
                              void* d_out, int out_size) {
    const float* base_feat = (const float*)d_in[0];
    const float* im_info   = (const float*)d_in[1];
    const float* conv_w    = (const float*)d_in[4];
    const float* conv_b    = (const float*)d_in[5];
    const float* cls_w     = (const float*)d_in[6];
    const float* cls_b     = (const float*)d_in[7];
    const float* bbox_w    = (const float*)d_in[8];
    const float* bbox_b    = (const float*)d_in[9];
    float* out = (float*)d_out;

    split_w<<<(CMID*CIN*9 + 255)/256, 256>>>(conv_w);
    size_t fsn = (size_t)3*BB*CIN*PPAD;
    split_feat<<<(unsigned)((fsn + 255)/256), 256>>>(base_feat);

    gemm_conv<<<4*104*BB, 256>>>(conv_b);

    size_t hsmem = (size_t)(54*512 + 64*96) * sizeof(float);
    cudaFuncSetAttribute(heads_kernel, cudaFuncAttributeMaxDynamicSharedMemorySize, (int)hsmem);
    heads_kernel<<<BB*HH, 288, hsmem>>>(cls_w, cls_b, bbox_w, bbox_b, im_info);

    void *d_temp, *dk, *dko, *dv, *dvo;
    cudaGetSymbolAddress(&d_temp, g_temp);
    cudaGetSymbolAddress(&dk, g_keys);
    cudaGetSymbolAddress(&dko, g_keys_out);
    cudaGetSymbolAddress(&dv, g_vals);
    cudaGetSymbolAddress(&dvo, g_vals_out);
    size_t temp_bytes = sizeof(g_temp);
    cub::DeviceRadixSort::SortPairs(d_temp, temp_bytes,
        (const unsigned long long*)dk, (unsigned long long*)dko,
        (const int*)dv, (int*)dvo, TOTAL, 0, 34, (cudaStream_t)0);

    gather_kernel<<<(BB*PRE + 255)/256, 256>>>();
    mask_kernel<<<(BB*PRE + 255)/256, 256>>>();
    nms_scan<<<BB, 32>>>(out);
    (void)in_sizes; (void)n_in; (void)out_size;
}

// round 16
// speedup vs baseline: 1.0855x; 1.0403x over previous
#include <cuda_runtime.h>
#include <cuda_fp16.h>
#include <cub/cub.cuh>

#define BB 4
#define CIN 1024
#define CMID 512
#define HH 64
#define WW 96
#define AA 9
#define NANCH (AA*HH*WW)
#define TOTAL (BB*NANCH)
#define PRE 6000
#define POST 300
#define MWORDS 94

#define PROW 104
#define PPAD 6912
#define PVALID 6864
#define KTOT 9216
#define NPASS 3
#define NSTG (NPASS*144)       /* 3 passes x 144 k-chunks of 64 */
#define DRAIN 18
#define SA_BYTES 16384         /* A: 128 rows x 128B */
#define SB_BYTES 8192          /* B: 64 k-rows x 128B (64 pos) */
#define STG (SA_BYTES + SB_BYTES)

__device__ __align__(256) __half g_fh[(size_t)2*3*BB*CIN*PPAD];   // [limb][dx][b][ci][PPAD]
__device__ __align__(256) __half g_wh[(size_t)2*CMID*KTOT];       // [limb][co][k]
__device__ __align__(256) float g_conv1p[(size_t)BB*CMID*PPAD];
__device__ float4 g_props[TOTAL];
__device__ unsigned long long g_keys[TOTAL];
__device__ unsigned long long g_keys_out[TOTAL];
__device__ int g_vals[TOTAL];
__device__ int g_vals_out[TOTAL];
__device__ float4 g_top[BB*PRE];
__device__ unsigned long long g_mask[(size_t)BB*PRE*MWORDS];
__device__ unsigned char g_temp[32u<<20];

__constant__ float c_WS[9] = {184.f,368.f,736.f,128.f,256.f,512.f, 88.f,176.f,352.f};
__constant__ float c_HS[9] = { 96.f,192.f,384.f,128.f,256.f,512.f,176.f,352.f,704.f};
__device__ const int PASS_SA[NPASS] = {0,0,1};
__device__ const int PASS_SB[NPASS] = {0,1,0};

__device__ __forceinline__ uint32_t smem_u32(const void* p) {
    uint32_t a;
    asm("{ .reg .u64 t; cvta.to.shared.u64 t, %1; cvt.u32.u64 %0, t; }" : "=r"(a) : "l"(p));
    return a;
}
#define CP16(d, g) asm volatile("cp.async.cg.shared.global [%0], [%1], 16;" :: "r"(d), "l"(g))
#define CPC()  asm volatile("cp.async.commit_group;" ::: "memory")
#define CPW1() asm volatile("cp.async.wait_group 1;" ::: "memory")
#define CPW0() asm volatile("cp.async.wait_group 0;" ::: "memory")
#define LDSM4(r, a) asm volatile("ldmatrix.sync.aligned.m8n8.x4.shared.b16 {%0,%1,%2,%3}, [%4];" \
    : "=r"((r)[0]), "=r"((r)[1]), "=r"((r)[2]), "=r"((r)[3]) : "r"(a))
#define LDSM4T(r, a) asm volatile("ldmatrix.sync.aligned.m8n8.x4.trans.shared.b16 {%0,%1,%2,%3}, [%4];" \
    : "=r"((r)[0]), "=r"((r)[1]), "=r"((r)[2]), "=r"((r)[3]) : "r"(a))
#define MMA(c, a, b0, b1) asm volatile( \
    "mma.sync.aligned.m16n8k16.row.col.f32.f16.f16.f32 {%0,%1,%2,%3},{%4,%5,%6,%7},{%8,%9},{%0,%1,%2,%3};" \
    : "+f"((c)[0]), "+f"((c)[1]), "+f"((c)[2]), "+f"((c)[3]) \
    : "r"((a)[0]), "r"((a)[1]), "r"((a)[2]), "r"((a)[3]), "r"(b0), "r"(b1))

// ---- P0: 2-limb weight split (x 2^12) ----
__global__ void split_w(const float* __restrict__ conv_w) {
    int idx = blockIdx.x * blockDim.x + threadIdx.x;
    if (idx >= CMID*CIN*9) return;
    int tap = idx % 9;
    int r = idx / 9;
    int ci = r % CIN, co = r / CIN;
    float xs = conv_w[idx] * 4096.f;
    __half h1 = __float2half_rn(xs);
    __half h2 = __float2half_rn(xs - __half2float(h1));
    size_t o = (size_t)co*KTOT + tap*CIN + ci;
    g_wh[o] = h1;
    g_wh[(size_t)CMID*KTOT + o] = h2;
}

// ---- P1: 2-limb feature split (x 2^12), 8-wide vectorized stores ----
__global__ void split_feat(const float* __restrict__ feat) {
    size_t idx = (size_t)blockIdx.x * blockDim.x + threadIdx.x;
    const size_t NQ8 = PPAD / 8;
    if (idx >= (size_t)3*BB*CIN*NQ8) return;
    int q0 = (int)(idx % NQ8) * 8;
    size_t r = idx / NQ8;
    int ci = (int)(r % CIN); r /= CIN;
    int b = (int)(r % BB);
    int dx = (int)(r / BB);
    const float* frow = feat + (((size_t)b*CIN + ci)*HH)*WW;
    __half h1[8], h2[8];
    #pragma unroll
    for (int u = 0; u < 8; ++u) {
        int j = q0 + u + dx;
        float x = 0.f;
        int hp = j / PROW, wp = j % PROW;
        if (j < PVALID && hp >= 1 && hp <= HH && wp >= 1 && wp <= WW)
            x = frow[(size_t)(hp - 1)*WW + wp - 1];
        x *= 4096.f;
        h1[u] = __float2half_rn(x);
        h2[u] = __float2half_rn(x - __half2float(h1[u]));
    }
    size_t ss = (size_t)3*BB*CIN*PPAD;
    size_t o = (((size_t)dx*BB + b)*CIN + ci)*PPAD + q0;
    *(uint4*)(g_fh + o)      = *(const uint4*)h1;
    *(uint4*)(g_fh + ss + o) = *(const uint4*)h2;
}

// ---- K1: implicit-GEMM conv, HMMA BK=64 128x64 tile, 2 CTAs/SM ----
__device__ __forceinline__ void stage_src(int s, int b, int co0, int pos0,
                                          const __half*& gA, const __half*& gB) {
    int p = s / 144, ks = s - p*144;
    int k0 = ks * 64;
    int tap = k0 >> 10, ci0 = k0 & 1023;
    int dy = tap / 3, dx = tap - dy*3;
    int sa = PASS_SA[p], sb = PASS_SB[p];
    gA = g_wh + (size_t)sa*CMID*KTOT + (size_t)co0*KTOT + k0;
    gB = g_fh + (size_t)sb*((size_t)3*BB*CIN*PPAD) +
         (((size_t)dx*BB + b)*CIN + ci0)*PPAD + pos0 + dy*PROW;
}

__device__ __forceinline__ void load_stage(uint32_t sbuf,
                                           const __half* gA, const __half* gB, int t) {
    #pragma unroll
    for (int i = 0; i < 4; ++i) {            // A: 128 rows x 128B, 16B chunks
        int id = t + i*256, row = id >> 3, c = id & 7;
        CP16(sbuf + row*128 + ((c*16) ^ ((row & 7) << 4)), gA + (size_t)row*KTOT + c*8);
    }
    #pragma unroll
    for (int i = 0; i < 2; ++i) {            // B: 64 k-rows x 128B, 16B chunks
        int id = t + i*256, k = id >> 3, c = id & 7;
        CP16(sbuf + SA_BYTES + k*128 + ((c*16) ^ ((k & 7) << 4)), gB + (size_t)k*PPAD + c*8);
    }
}

__global__ __launch_bounds__(256, 2) void gemm_conv(const float* __restrict__ bias) {
    __shared__ __align__(256) char smem[2*STG];   // 48KB static, 2 CTAs/SM
    const uint32_t sbase = smem_u32(smem);
    const int t = threadIdx.x, lane = t & 31, wid = t >> 5;
    const int wm = wid & 1, wn = wid >> 1;   // warp tile: 64co x 16pos
    const int cot = blockIdx.x & 3;
    const int rest = blockIdx.x >> 2;
    const int post = rest % 104;
    const int b = rest / 104;
    const int co0 = cot*128, pos0 = post*64;

    float acc[4][2][4];
    float accS[4][2][4];
    #pragma unroll
    for (int i = 0; i < 4; ++i)
        #pragma unroll
        for (int j = 0; j < 2; ++j)
            #pragma unroll
            for (int k = 0; k < 4; ++k) { acc[i][j][k] = 0.f; accS[i][j][k] = 0.f; }

    const __half *gA, *gB;
    stage_src(0, b, co0, pos0, gA, gB);
    load_stage(sbase, gA, gB, t);
    CPC();

    for (int s = 0; s < NSTG; ++s) {
        const int buf = s & 1;
        if (s + 1 < NSTG) {
            stage_src(s + 1, b, co0, pos0, gA, gB);
            load_stage(sbase + ((s + 1) & 1)*STG, gA, gB, t);
            CPC();
            CPW1();
        } else {
            CPW0();
        }
        __syncthreads();
        const uint32_t sA = sbase + buf*STG, sB = sA + SA_BYTES;
        #pragma unroll
        for (int kk = 0; kk < 4; ++kk) {
            uint32_t a[4][4], bb[4];
            #pragma unroll
            for (int i = 0; i < 4; ++i) {
                int row = wm*64 + i*16 + (lane & 15);
                uint32_t ad = sA + row*128 +
                    (((kk*32) + ((lane >> 4) << 4)) ^ ((row & 7) << 4));
                LDSM4(a[i], ad);
            }
            {
                int kr = kk*16 + (lane & 15);
                uint32_t nb = wn*32 + ((lane >> 4) << 4);
                uint32_t ad = sB + kr*128 + (nb ^ ((kr & 7) << 4));
                LDSM4T(bb, ad);
            }
            #pragma unroll
            for (int i = 0; i < 4; ++i) {
                MMA(acc[i][0], a[i], bb[0], bb[1]);
                MMA(acc[i][1], a[i], bb[2], bb[3]);
            }
        }
        if ((s % DRAIN) == DRAIN - 1) {
            #pragma unroll
            for (int i = 0; i < 4; ++i)
                #pragma unroll
                for (int j = 0; j < 2; ++j)
                    #pragma unroll
                    for (int k = 0; k < 4; ++k) {
                        accS[i][j][k] += acc[i][j][k];
                        acc[i][j][k] = 0.f;
                    }
        }
        __syncthreads();
    }

    const float SC = 1.f / 16777216.f;       // 2^-24 (both operands x 2^12)
    #pragma unroll
    for (int i = 0; i < 4; ++i) {
        int co = co0 + wm*64 + i*16 + (lane >> 2);
        float bv0 = bias[co], bv8 = bias[co + 8];
        float* r0 = g_conv1p + ((size_t)b*CMID + co)*PPAD;
        #pragma unroll
        for (int j = 0; j < 2; ++j) {
            int pos = pos0 + wn*16 + j*8 + (lane & 3)*2;
            float2 v0, v1;
            v0.x = fmaxf(fmaf(accS[i][j][0] + acc[i][j][0], SC, bv0), 0.f);
            v0.y = fmaxf(fmaf(accS[i][j][1] + acc[i][j][1], SC, bv0), 0.f);
            v1.x = fmaxf(fmaf(accS[i][j][2] + acc[i][j][2], SC, bv8), 0.f);
            v1.y = fmaxf(fmaf(accS[i][j][3] + acc[i][j][3], SC, bv8), 0.f);
            *(float2*)(r0 + pos) = v0;
            *(float2*)(r0 + 8*PPAD + pos) = v1;
        }
    }
}

// ---- K2: 1x1 heads + softmax + decode + clip + sort keys ----
__global__ __launch_bounds__(288) void heads_kernel(const float* __restrict__ cls_w,
        const float* __restrict__ cls_b, const float* __restrict__ bbox_w,
        const float* __restrict__ bbox_b, const float* __restrict__ im_info) {
    extern __shared__ float sm[];
    float* wsm = sm;
    float* fsm = sm + 54*512;
    const int b = blockIdx.x / HH, h = blockIdx.x % HH;
    const int t = threadIdx.x, a = t / 32, lane = t % 32;

    for (int i = t; i < 18*512; i += 288) wsm[i] = cls_w[i];
    for (int i = t; i < 36*512; i += 288) wsm[18*512 + i] = bbox_w[i];

    float acc[6][3];
    #pragma unroll
    for (int o = 0; o < 6; ++o)
        #pragma unroll
        for (int q = 0; q < 3; ++q) acc[o][q] = 0.f;

    const float* w0 = wsm + a*512;
    const float* w1 = wsm + (a+9)*512;
    const float* wd = wsm + (18 + a*4)*512;

    for (int ct = 0; ct < 8; ++ct) {
        __syncthreads();
        for (int i = t; i < 64*96; i += 288)
            fsm[i] = g_conv1p[((size_t)b*CMID + ct*64 + i/96)*PPAD + h*PROW + (i%96)];
        __syncthreads();
        #pragma unroll 4
        for (int cl = 0; cl < 64; ++cl) {
            int ch = ct*64 + cl;
            float v0 = w0[ch], v1 = w1[ch];
            float v2 = wd[ch], v3 = wd[512+ch], v4 = wd[1024+ch], v5 = wd[1536+ch];
            #pragma unroll
            for (int q = 0; q < 3; ++q) {
                float f = fsm[cl*96 + lane + q*32];
                acc[0][q] = fmaf(v0, f, acc[0][q]);
                acc[1][q] = fmaf(v1, f, acc[1][q]);
                acc[2][q] = fmaf(v2, f, acc[2][q]);
                acc[3][q] = fmaf(v3, f, acc[3][q]);
                acc[4][q] = fmaf(v4, f, acc[4][q]);
                acc[5][q] = fmaf(v5, f, acc[5][q]);
            }
        }
    }
    const float imh = im_info[b*3+0] - 1.f, imw = im_info[b*3+1] - 1.f;
    const float cb0 = cls_b[a], cb1 = cls_b[a+9];
    const float bb0 = bbox_b[a*4+0], bb1 = bbox_b[a*4+1];
    const float bb2 = bbox_b[a*4+2], bb3 = bbox_b[a*4+3];
    const float ws_ = c_WS[a], hs_ = c_HS[a];
    #pragma unroll
    for (int q = 0; q < 3; ++q) {
        int w = lane + q*32;
        float s0 = acc[0][q] + cb0, s1 = acc[1][q] + cb1;
        float m = fmaxf(s0, s1);
        float e0 = expf(s0 - m), e1 = expf(s1 - m);
        float score = e1 / (e0 + e1);
        float d0 = acc[2][q] + bb0, d1 = acc[3][q] + bb1;
        float d2 = acc[4][q] + bb2, d3 = acc[5][q] + bb3;
        float ax1 = 16.f*w + (7.5f - 0.5f*(ws_-1.f));
        float ay1 = 16.f*h + (7.5f - 0.5f*(hs_-1.f));
        float cx = d0*ws_ + ax1 + 0.5f*ws_;
        float cy = d1*hs_ + ay1 + 0.5f*hs_;
        float pw = expf(d2)*ws_, ph = expf(d3)*hs_;
        float x1 = fminf(fmaxf(cx - 0.5f*pw, 0.f), imw);
        float y1 = fminf(fmaxf(cy - 0.5f*ph, 0.f), imh);
        float x2 = fminf(fmaxf(cx + 0.5f*pw, 0.f), imw);
        float y2 = fminf(fmaxf(cy + 0.5f*ph, 0.f), imh);
        int pidx = (h*WW + w)*AA + a;
        int gi = b*NANCH + pidx;
        g_props[gi] = make_float4(x1, y1, x2, y2);
        unsigned u = __float_as_uint(score);
        u = (u & 0x80000000u) ? ~u : (u | 0x80000000u);
        g_keys[gi] = ((unsigned long long)b << 32) | (unsigned)(~u);
        g_vals[gi] = pidx;
    }
}

__global__ void gather_kernel() {
    int t = blockIdx.x * blockDim.x + threadIdx.x;
    if (t >= BB*PRE) return;
    int b = t / PRE, r = t % PRE;
    g_top[t] = g_props[b*NANCH + g_vals_out[b*NANCH + r]];
}

// ---- K4: NMS mask, upper triangle only ----
__global__ __launch_bounds__(256) void mask_kernel() {
    int t = blockIdx.x * blockDim.x + threadIdx.x;
    if (t >= BB*PRE) return;
    int b = t / PRE, r = t % PRE;
    float4 bi = g_top[t];
    float ai = (bi.z - bi.x + 1.f) * (bi.w - bi.y + 1.f);
    const float4* base = g_top + b*PRE;
    unsigned long long* mrow = g_mask + (size_t)t*MWORDS;
    const int w0 = r >> 6;
    for (int w = 0; w < w0; ++w) mrow[w] = 0;
    unsigned long long word = 0;
    for (int j = w0 << 6; j < PRE; ++j) {
        float4 bj = __ldg(&base[j]);
        float xx1 = fmaxf(bi.x, bj.x), yy1 = fmaxf(bi.y, bj.y);
        float xx2 = fminf(bi.z, bj.z), yy2 = fminf(bi.w, bj.w);
        float inter = fmaxf(xx2 - xx1 + 1.f, 0.f) * fmaxf(yy2 - yy1 + 1.f, 0.f);
        float aj = (bj.z - bj.x + 1.f) * (bj.w - bj.y + 1.f);
        float iou = __fdiv_rn(inter, ai + aj - inter);
        if (!(iou <= 0.7f)) word |= (1ULL << (j & 63));
        if ((j & 63) == 63) {
            if ((j >> 6) == w0) word &= ~((1ULL << (r & 63)) - 1ULL);
            mrow[j >> 6] = word;
            word = 0;
        }
    }
    mrow[MWORDS - 1] = word;
}

__device__ __forceinline__ unsigned long long shfl64(unsigned long long v, int src) {
    return __shfl_sync(0xffffffffu, v, src);
}

__global__ void nms_scan(float* __restrict__ out) {
    const int b = blockIdx.x, lane = threadIdx.x;
    __shared__ int keeps[POST];
    const unsigned long long* mbase = g_mask + (size_t)b*PRE*MWORDS;
    unsigned long long r0 = 0, r1 = 0, r2 = 0;
    int cnt = 0;
    for (int w = 0; w < MWORDS && cnt < POST; ++w) {
        int src = w & 31;
        unsigned long long cur = (w < 32) ? r0 : (w < 64 ? r1 : r2);
        unsigned long long avail = ~shfl64(cur, src);
        if (w == MWORDS - 1) avail &= (1ULL << 48) - 1;
        while (avail && cnt < POST) {
            int bit = __ffsll((long long)avail) - 1;
            int i = (w << 6) + bit;
            keeps[cnt++] = i;
            const unsigned long long* row = mbase + (size_t)i*MWORDS;
            r0 |= row[lane];
            r1 |= row[lane + 32];
            if (lane < 30) r2 |= row[lane + 64];
            unsigned long long cur2 = (w < 32) ? r0 : (w < 64 ? r1 : r2);
            avail &= ~shfl64(cur2, src);
        }
    }
    __syncwarp();
    for (int k = lane; k < POST; k += 32) {
        float4 bx = make_float4(0.f, 0.f, 0.f, 0.f);
        if (k < cnt) bx = g_top[b*PRE + keeps[k]];
        float* o = out + ((size_t)b*POST + k)*5;
        o[0] = (float)b; o[1] = bx.x; o[2] = bx.y; o[3] = bx.z; o[4] = bx.w;
    }
}

extern "C" void kernel_launch(void* const* d_in, const int* in_sizes, int n_in,
                              void* d_out, int out_size) {
    const float* base_feat = (const float*)d_in[0];
    const float* im_info   = (const float*)d_in[1];
    const float* conv_w    = (const float*)d_in[4];
    const float* conv_b    = (const float*)d_in[5];
    const float* cls_w     = (const float*)d_in[6];
    const float* cls_b     = (const float*)d_in[7];
    const float* bbox_w    = (const float*)d_in[8];
    const float* bbox_b    = (const float*)d_in[9];
    float* out = (float*)d_out;

    split_w<<<(CMID*CIN*9 + 255)/256, 256>>>(conv_w);
    size_t fsn = (size_t)3*BB*CIN*(PPAD/8);
    split_feat<<<(unsigned)((fsn + 255)/256), 256>>>(base_feat);

    gemm_conv<<<4*104*BB, 256>>>(conv_b);

    size_t hsmem = (size_t)(54*512 + 64*96) * sizeof(float);
    cudaFuncSetAttribute(heads_kernel, cudaFuncAttributeMaxDynamicSharedMemorySize, (int)hsmem);
    heads_kernel<<<BB*HH, 288, hsmem>>>(cls_w, cls_b, bbox_w, bbox_b, im_info);

    void *d_temp, *dk, *dko, *dv, *dvo;
    cudaGetSymbolAddress(&d_temp, g_temp);
    cudaGetSymbolAddress(&dk, g_keys);
    cudaGetSymbolAddress(&dko, g_keys_out);
    cudaGetSymbolAddress(&dv, g_vals);
    cudaGetSymbolAddress(&dvo, g_vals_out);
    size_t temp_bytes = sizeof(g_temp);
    cub::DeviceRadixSort::SortPairs(d_temp, temp_bytes,
        (const unsigned long long*)dk, (unsigned long long*)dko,
        (const int*)dv, (int*)dvo, TOTAL, 0, 34, (cudaStream_t)0);

    gather_kernel<<<(BB*PRE + 255)/256, 256>>>();
    mask_kernel<<<(BB*PRE + 255)/256, 256>>>();
    nms_scan<<<BB, 32>>>(out);
    (void)in_sizes; (void)n_in; (void)out_size;
}